// round 6
// baseline (speedup 1.0000x reference)
#include <cuda_runtime.h>
#include <cuda_fp16.h>
#include <cstdint>

// ---------------------------------------------------------------------------
// int4 group-quantized GEMM via mma.sync (HMMA), fp32 I/O.
// y[512, 11008] = x[512, 4096] @ dequant(W)[11008, 4096]^T
// w = scale[n, k/128] * (q - 8), one packed byte per int32.
//
// R6: 4-warp CTA, 64x64 warp tile (2x2 warp grid) -> LDSM traffic per MAC
// drops ~35% vs 8-warp 64x32; 2 CTAs/SM, 3-buf cp.async A, reg-prefetch B.
// ---------------------------------------------------------------------------

#define M_TOTAL 512
#define N_TOTAL 11008
#define K_TOTAL 4096
#define KW_INT  2048
#define NGROUPS 32

#define MT 128
#define NT 128
#define KT 64
#define NSTAGES (K_TOTAL / KT)  // 64
#define THREADS 128

#define SWZ128(bo) ((bo) ^ (((bo) >> 3) & 0x70))

#define STAGE_BYTES (128 * 128)                    // 16 KB
#define SMEM_A_OFF(buf) ((buf) * STAGE_BYTES)      // 3 buffers
#define SMEM_B_OFF(buf) (3 * STAGE_BYTES + (buf) * STAGE_BYTES)  // 2 buffers
#define SMEM_TOTAL (5 * STAGE_BYTES)               // 80 KB

__device__ __align__(16) __half g_xh[M_TOTAL * K_TOTAL];   // 4 MB
__device__ __align__(16) __half g_sh[N_TOTAL * NGROUPS];   // 0.69 MB

// ---------------- PTX helpers ----------------
__device__ __forceinline__ uint32_t smem_u32(const void* p) {
    uint32_t a;
    asm("{ .reg .u64 t; cvta.to.shared.u64 t, %1; cvt.u32.u64 %0, t; }"
        : "=r"(a) : "l"(p));
    return a;
}

__device__ __forceinline__ void cp_async16(uint32_t saddr, const void* g) {
    asm volatile("cp.async.cg.shared.global [%0], [%1], 16;"
                 :: "r"(saddr), "l"(g) : "memory");
}
#define CP_COMMIT() asm volatile("cp.async.commit_group;" ::: "memory")
#define CP_WAIT1()  asm volatile("cp.async.wait_group 1;" ::: "memory")

__device__ __forceinline__ void ldsm4(uint32_t* r, uint32_t a) {
    asm volatile("ldmatrix.sync.aligned.m8n8.x4.shared.b16 {%0,%1,%2,%3}, [%4];"
                 : "=r"(r[0]), "=r"(r[1]), "=r"(r[2]), "=r"(r[3]) : "r"(a));
}

__device__ __forceinline__ void mma16816(float* c, const uint32_t* a,
                                         const uint32_t* b) {
    asm volatile(
        "mma.sync.aligned.m16n8k16.row.col.f32.f16.f16.f32 "
        "{%0,%1,%2,%3}, {%4,%5,%6,%7}, {%8,%9}, {%0,%1,%2,%3};"
        : "+f"(c[0]), "+f"(c[1]), "+f"(c[2]), "+f"(c[3])
        : "r"(a[0]), "r"(a[1]), "r"(a[2]), "r"(a[3]), "r"(b[0]), "r"(b[1]));
}

// dequant one packed byte -> half2 {lo-8, hi-8} * s2  (exact via 0x6400 bias)
__device__ __forceinline__ __half2 dq(int b, __half2 s2, __half2 c1032) {
    uint32_t u = (uint32_t)(b & 0xF) | (((uint32_t)b << 12) & 0x000F0000u)
               | 0x64006400u;
    __half2 h = __hsub2(*reinterpret_cast<__half2*>(&u), c1032);
    return __hmul2(h, s2);
}

// ---------------- fp32 -> fp16 conversion kernel ----------------
#define XV (M_TOTAL * K_TOTAL / 4)
#define SV (N_TOTAL * NGROUPS / 4)

__global__ void __launch_bounds__(256)
cvt_kernel(const float* __restrict__ x, const float* __restrict__ sc) {
    int i = blockIdx.x * blockDim.x + threadIdx.x;
    if (i < XV) {
        float4 f = reinterpret_cast<const float4*>(x)[i];
        union { __half2 h[2]; uint2 u; } p;
        p.h[0] = __floats2half2_rn(f.x, f.y);
        p.h[1] = __floats2half2_rn(f.z, f.w);
        reinterpret_cast<uint2*>(g_xh)[i] = p.u;
    } else if (i < XV + SV) {
        int j = i - XV;
        float4 f = reinterpret_cast<const float4*>(sc)[j];
        union { __half2 h[2]; uint2 u; } p;
        p.h[0] = __floats2half2_rn(f.x, f.y);
        p.h[1] = __floats2half2_rn(f.z, f.w);
        reinterpret_cast<uint2*>(g_sh)[j] = p.u;
    }
}

// ---------------- main GEMM kernel ----------------
__global__ void __launch_bounds__(THREADS, 2)
int4_gemm_hmma(const int* __restrict__ wp, float* __restrict__ y) {
    extern __shared__ __align__(1024) char smem[];
    const uint32_t sbase = smem_u32(smem);

    const int tid = threadIdx.x;
    const int wid = tid >> 5;
    const int lid = tid & 31;
    const int wm = (wid >> 1) * 64;   // 2x2 warp grid, 64x64 warp tile
    const int wn = (wid & 1) * 64;

    const int m0 = blockIdx.x * MT;   // fast dim: M-siblings share weights in L2
    const int n0 = blockIdx.y * NT;

    const int jA = lid >> 3, rA = lid & 7;
    const int a_row_l = (jA & 1) * 8 + rA;
    const int a_kb_l  = (jA >> 1) * 16;
    const int b_row_l = (jA >> 1) * 8 + rA;
    const int b_kb_l  = (jA & 1) * 16;

    const __half2 c1032 = __half2half2(__ushort_as_half((unsigned short)0x6408));

    float acc[4][8][4];
    #pragma unroll
    for (int i = 0; i < 4; ++i)
        #pragma unroll
        for (int j = 0; j < 8; ++j)
            #pragma unroll
            for (int k = 0; k < 4; ++k) acc[i][j][k] = 0.f;

    auto issue_a = [&](int k0, int buf) {
        const uint32_t abase = sbase + SMEM_A_OFF(buf);
        #pragma unroll
        for (int it = 0; it < 8; ++it) {
            int t = tid + it * THREADS;       // 0..1023
            int row = t >> 3, ch = t & 7;
            const void* src = g_xh + (size_t)(m0 + row) * K_TOTAL + k0 + ch * 8;
            uint32_t bo = row * 128 + ch * 16;
            cp_async16(abase + SWZ128(bo), src);
        }
    };

    // B producer: thread t owns weight row (n0 + t); 32 int32 = 8 x int4
    int4 bp[8];
    __half2 s2;
    auto load_b = [&](int k0) {
        const int4* gb = reinterpret_cast<const int4*>(
            wp + (size_t)(n0 + tid) * KW_INT + (k0 >> 1));
        #pragma unroll
        for (int j = 0; j < 8; ++j) bp[j] = gb[j];
        const __half s = g_sh[(size_t)(n0 + tid) * NGROUPS + (k0 >> 7)];
        s2 = __half2half2(s);
    };

    auto store_b = [&](int buf) {
        #pragma unroll
        for (int j = 0; j < 8; ++j) {
            union { __half2 h[4]; uint4 u; } pk;
            pk.h[0] = dq(bp[j].x, s2, c1032);
            pk.h[1] = dq(bp[j].y, s2, c1032);
            pk.h[2] = dq(bp[j].z, s2, c1032);
            pk.h[3] = dq(bp[j].w, s2, c1032);
            uint32_t bo = (uint32_t)tid * 128 + j * 16;
            *reinterpret_cast<uint4*>(smem + SMEM_B_OFF(buf) + SWZ128(bo)) = pk.u;
        }
    };

    // ---- prologue ----
    issue_a(0, 0);
    CP_COMMIT();
    issue_a(KT, 1);
    CP_COMMIT();
    load_b(0);
    store_b(0);
    CP_WAIT1();
    __syncthreads();

    // ---- main loop ----
    int abuf_c = 0;
    int abuf_p = 2;
    #pragma unroll 1
    for (int st = 0; st < NSTAGES; ++st) {
        if (st + 2 < NSTAGES) issue_a((st + 2) * KT, abuf_p);
        CP_COMMIT();
        if (st + 1 < NSTAGES) load_b((st + 1) * KT);

        const uint32_t abase = sbase + SMEM_A_OFF(abuf_c);
        const uint32_t bbase = sbase + SMEM_B_OFF(st & 1);
        #pragma unroll
        for (int ks = 0; ks < 4; ++ks) {
            const int kb = ks * 32;
            uint32_t af[4][4];
            #pragma unroll
            for (int mt = 0; mt < 4; ++mt) {
                uint32_t bo = (uint32_t)(wm + mt * 16 + a_row_l) * 128
                            + kb + a_kb_l;
                ldsm4(af[mt], abase + SWZ128(bo));
            }
            uint32_t bf[4][4];
            #pragma unroll
            for (int np = 0; np < 4; ++np) {
                uint32_t bo = (uint32_t)(wn + np * 16 + b_row_l) * 128
                            + kb + b_kb_l;
                ldsm4(bf[np], bbase + SWZ128(bo));
            }
            #pragma unroll
            for (int mt = 0; mt < 4; ++mt)
                #pragma unroll
                for (int nt = 0; nt < 8; ++nt)
                    mma16816(acc[mt][nt], af[mt], &bf[nt >> 1][(nt & 1) * 2]);
        }

        if (st + 1 < NSTAGES) store_b((st + 1) & 1);
        CP_WAIT1();
        __syncthreads();

        abuf_c = (abuf_c == 2) ? 0 : abuf_c + 1;
        abuf_p = (abuf_p == 2) ? 0 : abuf_p + 1;
    }

    // ---- epilogue: fp32 accum -> fp16-rounded -> fp32 stores ----
    const int crow = lid >> 2;
    const int ccol = (lid & 3) * 2;
    #pragma unroll
    for (int mt = 0; mt < 4; ++mt) {
        #pragma unroll
        for (int nt = 0; nt < 8; ++nt) {
            const int r = m0 + wm + mt * 16 + crow;
            const int c = n0 + wn + nt * 8 + ccol;
            float v0 = __half2float(__float2half_rn(acc[mt][nt][0]));
            float v1 = __half2float(__float2half_rn(acc[mt][nt][1]));
            float v2 = __half2float(__float2half_rn(acc[mt][nt][2]));
            float v3 = __half2float(__float2half_rn(acc[mt][nt][3]));
            *reinterpret_cast<float2*>(y + (size_t)r * N_TOTAL + c) =
                make_float2(v0, v1);
            *reinterpret_cast<float2*>(y + (size_t)(r + 8) * N_TOTAL + c) =
                make_float2(v2, v3);
        }
    }
}

extern "C" void kernel_launch(void* const* d_in, const int* in_sizes, int n_in,
                              void* d_out, int out_size) {
    const float* x      = (const float*)d_in[0];
    const int*   wp     = (const int*)d_in[1];
    const float* scales = (const float*)d_in[2];
    float*       y      = (float*)d_out;

    int nconv = XV + SV;
    cvt_kernel<<<(nconv + 255) / 256, 256>>>(x, scales);

    cudaFuncSetAttribute(int4_gemm_hmma,
                         cudaFuncAttributeMaxDynamicSharedMemorySize,
                         SMEM_TOTAL);
    dim3 grid(M_TOTAL / MT, N_TOTAL / NT);   // (4, 86)
    int4_gemm_hmma<<<grid, THREADS, SMEM_TOTAL>>>(wp, y);
}

// round 9
// speedup vs baseline: 1.0647x; 1.0647x over previous
#include <cuda_runtime.h>
#include <cuda_fp16.h>
#include <cstdint>

// ---------------------------------------------------------------------------
// int4 group-quantized GEMM via mma.sync (HMMA), fp32 I/O.
// y[512, 11008] = x[512, 4096] @ dequant(W)[11008, 4096]^T
// w = scale[n, k/128] * (q - 8), one packed byte per int32.
//
// R8 = R7 resubmit (infra failure last round):
//  - 8-warp 64x32 warp tiles, 2 CTAs/SM
//  - ks-level fragment double-buffering (LDSM for ks+1 overlaps MMAs of ks)
//  - B raw packed ints staged via cp.async (2-buf SMEM) instead of registers
// ---------------------------------------------------------------------------

#define M_TOTAL 512
#define N_TOTAL 11008
#define K_TOTAL 4096
#define KW_INT  2048
#define NGROUPS 32

#define MT 128
#define NT 128
#define KT 64
#define NSTAGES (K_TOTAL / KT)  // 64
#define THREADS 256

#define SWZ128(bo) ((bo) ^ (((bo) >> 3) & 0x70))

#define STAGE_BYTES 16384
#define SMEM_A_OFF(buf)    ((buf) * STAGE_BYTES)                 // 3 bufs
#define SMEM_BF_OFF(buf)   (3 * STAGE_BYTES + (buf) * STAGE_BYTES)   // 2 bufs
#define SMEM_BRAW_OFF(buf) (5 * STAGE_BYTES + (buf) * STAGE_BYTES)   // 2 bufs
#define SMEM_TOTAL (7 * STAGE_BYTES)   // 112 KB

__device__ __align__(16) __half g_xh[M_TOTAL * K_TOTAL];   // 4 MB
__device__ __align__(16) __half g_sh[N_TOTAL * NGROUPS];   // 0.69 MB

// ---------------- PTX helpers ----------------
__device__ __forceinline__ uint32_t smem_u32(const void* p) {
    uint32_t a;
    asm("{ .reg .u64 t; cvta.to.shared.u64 t, %1; cvt.u32.u64 %0, t; }"
        : "=r"(a) : "l"(p));
    return a;
}

__device__ __forceinline__ void cp_async16(uint32_t saddr, const void* g) {
    asm volatile("cp.async.cg.shared.global [%0], [%1], 16;"
                 :: "r"(saddr), "l"(g) : "memory");
}
#define CP_COMMIT() asm volatile("cp.async.commit_group;" ::: "memory")
#define CP_WAIT1()  asm volatile("cp.async.wait_group 1;" ::: "memory")

__device__ __forceinline__ void ldsm4(uint32_t* r, uint32_t a) {
    asm volatile("ldmatrix.sync.aligned.m8n8.x4.shared.b16 {%0,%1,%2,%3}, [%4];"
                 : "=r"(r[0]), "=r"(r[1]), "=r"(r[2]), "=r"(r[3]) : "r"(a));
}

__device__ __forceinline__ void mma16816(float* c, const uint32_t* a,
                                         const uint32_t* b) {
    asm volatile(
        "mma.sync.aligned.m16n8k16.row.col.f32.f16.f16.f32 "
        "{%0,%1,%2,%3}, {%4,%5,%6,%7}, {%8,%9}, {%0,%1,%2,%3};"
        : "+f"(c[0]), "+f"(c[1]), "+f"(c[2]), "+f"(c[3])
        : "r"(a[0]), "r"(a[1]), "r"(a[2]), "r"(a[3]), "r"(b[0]), "r"(b[1]));
}

// dequant one packed byte -> half2 {lo-8, hi-8} * s2  (exact via 0x6400 bias)
__device__ __forceinline__ __half2 dq(int b, __half2 s2, __half2 c1032) {
    uint32_t u = (uint32_t)(b & 0xF) | (((uint32_t)b << 12) & 0x000F0000u)
               | 0x64006400u;
    __half2 h = __hsub2(*reinterpret_cast<__half2*>(&u), c1032);
    return __hmul2(h, s2);
}

// ---------------- fp32 -> fp16 conversion kernel ----------------
#define XV (M_TOTAL * K_TOTAL / 4)
#define SV (N_TOTAL * NGROUPS / 4)

__global__ void __launch_bounds__(256)
cvt_kernel(const float* __restrict__ x, const float* __restrict__ sc) {
    int i = blockIdx.x * blockDim.x + threadIdx.x;
    if (i < XV) {
        float4 f = reinterpret_cast<const float4*>(x)[i];
        union { __half2 h[2]; uint2 u; } p;
        p.h[0] = __floats2half2_rn(f.x, f.y);
        p.h[1] = __floats2half2_rn(f.z, f.w);
        reinterpret_cast<uint2*>(g_xh)[i] = p.u;
    } else if (i < XV + SV) {
        int j = i - XV;
        float4 f = reinterpret_cast<const float4*>(sc)[j];
        union { __half2 h[2]; uint2 u; } p;
        p.h[0] = __floats2half2_rn(f.x, f.y);
        p.h[1] = __floats2half2_rn(f.z, f.w);
        reinterpret_cast<uint2*>(g_sh)[j] = p.u;
    }
}

// ---------------- main GEMM kernel ----------------
__global__ void __launch_bounds__(THREADS, 2)
int4_gemm_hmma(const int* __restrict__ wp, float* __restrict__ y) {
    extern __shared__ __align__(1024) char smem[];
    const uint32_t sbase = smem_u32(smem);

    const int tid = threadIdx.x;
    const int wid = tid >> 5;
    const int lid = tid & 31;
    const int wm = (wid >> 2) * 64;   // 2x4 warp grid, 64x32 warp tile
    const int wn = (wid & 3) * 32;

    const int m0 = blockIdx.x * MT;   // fast dim: M-siblings share weights in L2
    const int n0 = blockIdx.y * NT;

    const int jA = lid >> 3, rA = lid & 7;
    const int a_row_l = (jA & 1) * 8 + rA;
    const int a_kb_l  = (jA >> 1) * 16;
    const int b_row_l = (jA >> 1) * 8 + rA;
    const int b_kb_l  = (jA & 1) * 16;

    const int brow = tid >> 1;        // weight row owned for dequant
    const int bseg = tid & 1;
    const __half2 c1032 = __half2half2(__ushort_as_half((unsigned short)0x6408));

    float acc[4][4][4];
    #pragma unroll
    for (int i = 0; i < 4; ++i)
        #pragma unroll
        for (int j = 0; j < 4; ++j)
            #pragma unroll
            for (int k = 0; k < 4; ++k) acc[i][j][k] = 0.f;

    auto issue_a = [&](int k0, int buf) {
        const uint32_t abase = sbase + SMEM_A_OFF(buf);
        #pragma unroll
        for (int it = 0; it < 4; ++it) {
            int t = tid + it * THREADS;
            int row = t >> 3, ch = t & 7;
            const void* src = g_xh + (size_t)(m0 + row) * K_TOTAL + k0 + ch * 8;
            uint32_t bo = row * 128 + ch * 16;
            cp_async16(abase + SWZ128(bo), src);
        }
    };

    // raw packed B: 128 rows x 128B = 16 KB/stage; thread t owns 4 x 16B
    // chunks at interleaved smem positions (i*256 + tid)*16 (bank-friendly).
    auto issue_braw = [&](int k0, int buf) {
        const uint32_t rbase = sbase + SMEM_BRAW_OFF(buf);
        const int* src = wp + (size_t)(n0 + brow) * KW_INT + (k0 >> 1)
                       + bseg * 16;
        #pragma unroll
        for (int i = 0; i < 4; ++i)
            cp_async16(rbase + (uint32_t)(i * 256 + tid) * 16, src + i * 4);
    };

    auto dequant = [&](int rbuf, int fbuf, __half2 s2) {
        #pragma unroll
        for (int i = 0; i < 4; ++i) {
            int4 pv = *reinterpret_cast<const int4*>(
                smem + SMEM_BRAW_OFF(rbuf) + (size_t)(i * 256 + tid) * 16);
            union { __half2 h[4]; uint4 u; } pk;
            pk.h[0] = dq(pv.x, s2, c1032);
            pk.h[1] = dq(pv.y, s2, c1032);
            pk.h[2] = dq(pv.z, s2, c1032);
            pk.h[3] = dq(pv.w, s2, c1032);
            uint32_t bo = (uint32_t)brow * 128 + bseg * 64 + i * 16;
            *reinterpret_cast<uint4*>(smem + SMEM_BF_OFF(fbuf) + SWZ128(bo)) =
                pk.u;
        }
    };

    const __half* srow = g_sh + (size_t)(n0 + brow) * NGROUPS;

    // ---- prologue ----
    issue_a(0, 0);
    issue_braw(0, 0);
    CP_COMMIT();                 // g0
    issue_a(KT, 1);
    issue_braw(KT, 1);
    CP_COMMIT();                 // g1
    CP_WAIT1();                  // g0 landed
    dequant(0, 0, __half2half2(srow[0]));
    __syncthreads();

    // ---- main loop ----
    int abuf_c = 0;
    int abuf_p = 2;
    #pragma unroll 1
    for (int st = 0; st < NSTAGES; ++st) {
        if (st + 2 < NSTAGES) {
            issue_a((st + 2) * KT, abuf_p);
            issue_braw((st + 2) * KT, st & 1);   // (st+2)&1 == st&1
        }
        CP_COMMIT();

        __half s_next;
        if (st + 1 < NSTAGES) s_next = srow[(st + 1) >> 1];

        // ---- compute stage st with ks-pipelined fragments ----
        const uint32_t abase = sbase + SMEM_A_OFF(abuf_c);
        const uint32_t bbase = sbase + SMEM_BF_OFF(st & 1);
        uint32_t af[2][4][4];
        uint32_t bf[2][2][4];
        #pragma unroll
        for (int mt = 0; mt < 4; ++mt)
            ldsm4(af[0][mt], abase + SWZ128(
                (uint32_t)(wm + mt * 16 + a_row_l) * 128 + a_kb_l));
        #pragma unroll
        for (int np = 0; np < 2; ++np)
            ldsm4(bf[0][np], bbase + SWZ128(
                (uint32_t)(wn + np * 16 + b_row_l) * 128 + b_kb_l));

        #pragma unroll
        for (int ks = 0; ks < 4; ++ks) {
            const int cur = ks & 1, nxt = cur ^ 1;
            if (ks < 3) {
                const int kb = (ks + 1) * 32;
                #pragma unroll
                for (int mt = 0; mt < 4; ++mt)
                    ldsm4(af[nxt][mt], abase + SWZ128(
                        (uint32_t)(wm + mt * 16 + a_row_l) * 128 + kb + a_kb_l));
                #pragma unroll
                for (int np = 0; np < 2; ++np)
                    ldsm4(bf[nxt][np], bbase + SWZ128(
                        (uint32_t)(wn + np * 16 + b_row_l) * 128 + kb + b_kb_l));
            }
            #pragma unroll
            for (int mt = 0; mt < 4; ++mt)
                #pragma unroll
                for (int nt = 0; nt < 4; ++nt)
                    mma16816(acc[mt][nt], af[cur][mt],
                             &bf[cur][nt >> 1][(nt & 1) * 2]);
        }

        CP_WAIT1();              // group(st+1) (A + Braw) landed
        if (st + 1 < NSTAGES)
            dequant((st + 1) & 1, (st + 1) & 1, __half2half2(s_next));
        __syncthreads();

        abuf_c = (abuf_c == 2) ? 0 : abuf_c + 1;
        abuf_p = (abuf_p == 2) ? 0 : abuf_p + 1;
    }

    // ---- epilogue: fp32 accum -> fp16-rounded -> fp32 stores ----
    const int crow = lid >> 2;
    const int ccol = (lid & 3) * 2;
    #pragma unroll
    for (int mt = 0; mt < 4; ++mt) {
        #pragma unroll
        for (int nt = 0; nt < 4; ++nt) {
            const int r = m0 + wm + mt * 16 + crow;
            const int c = n0 + wn + nt * 8 + ccol;
            float v0 = __half2float(__float2half_rn(acc[mt][nt][0]));
            float v1 = __half2float(__float2half_rn(acc[mt][nt][1]));
            float v2 = __half2float(__float2half_rn(acc[mt][nt][2]));
            float v3 = __half2float(__float2half_rn(acc[mt][nt][3]));
            *reinterpret_cast<float2*>(y + (size_t)r * N_TOTAL + c) =
                make_float2(v0, v1);
            *reinterpret_cast<float2*>(y + (size_t)(r + 8) * N_TOTAL + c) =
                make_float2(v2, v3);
        }
    }
}

extern "C" void kernel_launch(void* const* d_in, const int* in_sizes, int n_in,
                              void* d_out, int out_size) {
    const float* x      = (const float*)d_in[0];
    const int*   wp     = (const int*)d_in[1];
    const float* scales = (const float*)d_in[2];
    float*       y      = (float*)d_out;

    int nconv = XV + SV;
    cvt_kernel<<<(nconv + 255) / 256, 256>>>(x, scales);

    cudaFuncSetAttribute(int4_gemm_hmma,
                         cudaFuncAttributeMaxDynamicSharedMemorySize,
                         SMEM_TOTAL);
    dim3 grid(M_TOTAL / MT, N_TOTAL / NT);   // (4, 86)
    int4_gemm_hmma<<<grid, THREADS, SMEM_TOTAL>>>(wp, y);
}

// round 10
// speedup vs baseline: 1.3327x; 1.2517x over previous
#include <cuda_runtime.h>
#include <cuda_fp16.h>
#include <cstdint>

// ---------------------------------------------------------------------------
// int4 group-quantized GEMM via mma.sync (HMMA), fp32 I/O.
// y[512, 11008] = x[512, 4096] @ dequant(W)[11008, 4096]^T
// w = scale[n, k/128] * (q - 8); each int32 of weight_packed holds ONE byte
// (two nibbles: low = even k, high = odd k).
//
// R9 = R5 base (201us: 8-warp 64x32 tiles, 3-buf cp.async A, reg-prefetch B)
//      + per-warp ks-phase rotation: warp w starts its K-microstep loop at
//      ks = wid&3, so post-barrier LDSM bursts of different warps de-phase
//      and overlap other warps' MMA bursts. Zero register cost.
// ---------------------------------------------------------------------------

#define M_TOTAL 512
#define N_TOTAL 11008
#define K_TOTAL 4096
#define KW_INT  2048
#define NGROUPS 32

#define MT 128
#define NT 128
#define KT 64
#define NSTAGES (K_TOTAL / KT)  // 64
#define THREADS 256

#define SWZ128(bo) ((bo) ^ (((bo) >> 3) & 0x70))

#define STAGE_BYTES (128 * 128)                    // 16 KB
#define SMEM_A_OFF(buf) ((buf) * STAGE_BYTES)      // 3 buffers
#define SMEM_B_OFF(buf) (3 * STAGE_BYTES + (buf) * STAGE_BYTES)  // 2 buffers
#define SMEM_TOTAL (5 * STAGE_BYTES)               // 80 KB

__device__ __align__(16) __half g_xh[M_TOTAL * K_TOTAL];   // 4 MB
__device__ __align__(16) __half g_sh[N_TOTAL * NGROUPS];   // 0.69 MB

// ---------------- PTX helpers ----------------
__device__ __forceinline__ uint32_t smem_u32(const void* p) {
    uint32_t a;
    asm("{ .reg .u64 t; cvta.to.shared.u64 t, %1; cvt.u32.u64 %0, t; }"
        : "=r"(a) : "l"(p));
    return a;
}

__device__ __forceinline__ void cp_async16(uint32_t saddr, const void* g) {
    asm volatile("cp.async.cg.shared.global [%0], [%1], 16;"
                 :: "r"(saddr), "l"(g) : "memory");
}
#define CP_COMMIT() asm volatile("cp.async.commit_group;" ::: "memory")
#define CP_WAIT1()  asm volatile("cp.async.wait_group 1;" ::: "memory")

__device__ __forceinline__ void ldsm4(uint32_t* r, uint32_t a) {
    asm volatile("ldmatrix.sync.aligned.m8n8.x4.shared.b16 {%0,%1,%2,%3}, [%4];"
                 : "=r"(r[0]), "=r"(r[1]), "=r"(r[2]), "=r"(r[3]) : "r"(a));
}

__device__ __forceinline__ void mma16816(float* c, const uint32_t* a,
                                         const uint32_t* b) {
    asm volatile(
        "mma.sync.aligned.m16n8k16.row.col.f32.f16.f16.f32 "
        "{%0,%1,%2,%3}, {%4,%5,%6,%7}, {%8,%9}, {%0,%1,%2,%3};"
        : "+f"(c[0]), "+f"(c[1]), "+f"(c[2]), "+f"(c[3])
        : "r"(a[0]), "r"(a[1]), "r"(a[2]), "r"(a[3]), "r"(b[0]), "r"(b[1]));
}

// dequant one packed byte -> half2 {lo-8, hi-8} * s2  (exact via 0x6400 bias)
__device__ __forceinline__ __half2 dq(int b, __half2 s2, __half2 c1032) {
    uint32_t u = (uint32_t)(b & 0xF) | (((uint32_t)b << 12) & 0x000F0000u)
               | 0x64006400u;
    __half2 h = __hsub2(*reinterpret_cast<__half2*>(&u), c1032);
    return __hmul2(h, s2);
}

// ---------------- fp32 -> fp16 conversion kernel ----------------
#define XV (M_TOTAL * K_TOTAL / 4)
#define SV (N_TOTAL * NGROUPS / 4)

__global__ void __launch_bounds__(256)
cvt_kernel(const float* __restrict__ x, const float* __restrict__ sc) {
    int i = blockIdx.x * blockDim.x + threadIdx.x;
    if (i < XV) {
        float4 f = reinterpret_cast<const float4*>(x)[i];
        union { __half2 h[2]; uint2 u; } p;
        p.h[0] = __floats2half2_rn(f.x, f.y);
        p.h[1] = __floats2half2_rn(f.z, f.w);
        reinterpret_cast<uint2*>(g_xh)[i] = p.u;
    } else if (i < XV + SV) {
        int j = i - XV;
        float4 f = reinterpret_cast<const float4*>(sc)[j];
        union { __half2 h[2]; uint2 u; } p;
        p.h[0] = __floats2half2_rn(f.x, f.y);
        p.h[1] = __floats2half2_rn(f.z, f.w);
        reinterpret_cast<uint2*>(g_sh)[j] = p.u;
    }
}

// ---------------- main GEMM kernel ----------------
__global__ void __launch_bounds__(THREADS, 2)
int4_gemm_hmma(const int* __restrict__ wp, float* __restrict__ y) {
    extern __shared__ __align__(1024) char smem[];
    const uint32_t sbase = smem_u32(smem);

    const int tid = threadIdx.x;
    const int wid = tid >> 5;
    const int lid = tid & 31;
    const int wm = (wid >> 2) * 64;   // 2x4 warp grid, 64x32 warp tile
    const int wn = (wid & 3) * 32;
    const int ksr = wid & 3;          // per-warp ks phase rotation

    const int m0 = blockIdx.x * MT;   // fast dim: M-siblings share weights in L2
    const int n0 = blockIdx.y * NT;

    const int jA = lid >> 3, rA = lid & 7;
    const int a_row_l = (jA & 1) * 8 + rA;
    const int a_kb_l  = (jA >> 1) * 16;
    const int b_row_l = (jA >> 1) * 8 + rA;
    const int b_kb_l  = (jA & 1) * 16;

    const int brow = tid >> 1;
    const int bseg = tid & 1;
    const __half2 c1032 = __half2half2(__ushort_as_half((unsigned short)0x6408));

    float acc[4][4][4];
    #pragma unroll
    for (int i = 0; i < 4; ++i)
        #pragma unroll
        for (int j = 0; j < 4; ++j)
            #pragma unroll
            for (int k = 0; k < 4; ++k) acc[i][j][k] = 0.f;

    auto issue_a = [&](int k0, int buf) {
        const uint32_t abase = sbase + SMEM_A_OFF(buf);
        #pragma unroll
        for (int it = 0; it < 4; ++it) {
            int t = tid + it * THREADS;
            int row = t >> 3, ch = t & 7;
            const void* src = g_xh + (size_t)(m0 + row) * K_TOTAL + k0 + ch * 8;
            uint32_t bo = row * 128 + ch * 16;
            cp_async16(abase + SWZ128(bo), src);
        }
    };

    int4 bp[4];
    __half2 s2;
    auto load_b = [&](int k0) {
        const int4* gb = reinterpret_cast<const int4*>(
            wp + (size_t)(n0 + brow) * KW_INT + (k0 >> 1) + bseg * 16);
        #pragma unroll
        for (int j = 0; j < 4; ++j) bp[j] = gb[j];
        const __half s = g_sh[(size_t)(n0 + brow) * NGROUPS + (k0 >> 7)];
        s2 = __half2half2(s);
    };

    auto store_b = [&](int buf) {
        #pragma unroll
        for (int j = 0; j < 4; ++j) {
            union { __half2 h[4]; uint4 u; } pk;
            pk.h[0] = dq(bp[j].x, s2, c1032);
            pk.h[1] = dq(bp[j].y, s2, c1032);
            pk.h[2] = dq(bp[j].z, s2, c1032);
            pk.h[3] = dq(bp[j].w, s2, c1032);
            uint32_t bo = (uint32_t)brow * 128 + bseg * 64 + j * 16;
            *reinterpret_cast<uint4*>(smem + SMEM_B_OFF(buf) + SWZ128(bo)) = pk.u;
        }
    };

    // ---- prologue ----
    issue_a(0, 0);
    CP_COMMIT();
    issue_a(KT, 1);
    CP_COMMIT();
    load_b(0);
    store_b(0);
    CP_WAIT1();
    __syncthreads();

    // ---- main loop ----
    int abuf_c = 0;
    int abuf_p = 2;
    #pragma unroll 1
    for (int st = 0; st < NSTAGES; ++st) {
        if (st + 2 < NSTAGES) issue_a((st + 2) * KT, abuf_p);
        CP_COMMIT();
        if (st + 1 < NSTAGES) load_b((st + 1) * KT);

        const uint32_t abase = sbase + SMEM_A_OFF(abuf_c);
        const uint32_t bbase = sbase + SMEM_B_OFF(st & 1);
        #pragma unroll
        for (int i = 0; i < 4; ++i) {
            const int ks = (i + ksr) & 3;     // rotated K-microstep order
            const int kb = ks * 32;
            uint32_t af[4][4];
            #pragma unroll
            for (int mt = 0; mt < 4; ++mt) {
                uint32_t bo = (uint32_t)(wm + mt * 16 + a_row_l) * 128
                            + kb + a_kb_l;
                ldsm4(af[mt], abase + SWZ128(bo));
            }
            uint32_t bf[2][4];
            #pragma unroll
            for (int np = 0; np < 2; ++np) {
                uint32_t bo = (uint32_t)(wn + np * 16 + b_row_l) * 128
                            + kb + b_kb_l;
                ldsm4(bf[np], bbase + SWZ128(bo));
            }
            #pragma unroll
            for (int mt = 0; mt < 4; ++mt)
                #pragma unroll
                for (int nt = 0; nt < 4; ++nt)
                    mma16816(acc[mt][nt], af[mt], &bf[nt >> 1][(nt & 1) * 2]);
        }

        if (st + 1 < NSTAGES) store_b((st + 1) & 1);
        CP_WAIT1();
        __syncthreads();

        abuf_c = (abuf_c == 2) ? 0 : abuf_c + 1;
        abuf_p = (abuf_p == 2) ? 0 : abuf_p + 1;
    }

    // ---- epilogue: fp32 accum -> fp16-rounded -> fp32 stores ----
    const int crow = lid >> 2;
    const int ccol = (lid & 3) * 2;
    #pragma unroll
    for (int mt = 0; mt < 4; ++mt) {
        #pragma unroll
        for (int nt = 0; nt < 4; ++nt) {
            const int r = m0 + wm + mt * 16 + crow;
            const int c = n0 + wn + nt * 8 + ccol;
            float v0 = __half2float(__float2half_rn(acc[mt][nt][0]));
            float v1 = __half2float(__float2half_rn(acc[mt][nt][1]));
            float v2 = __half2float(__float2half_rn(acc[mt][nt][2]));
            float v3 = __half2float(__float2half_rn(acc[mt][nt][3]));
            *reinterpret_cast<float2*>(y + (size_t)r * N_TOTAL + c) =
                make_float2(v0, v1);
            *reinterpret_cast<float2*>(y + (size_t)(r + 8) * N_TOTAL + c) =
                make_float2(v2, v3);
        }
    }
}

extern "C" void kernel_launch(void* const* d_in, const int* in_sizes, int n_in,
                              void* d_out, int out_size) {
    const float* x      = (const float*)d_in[0];
    const int*   wp     = (const int*)d_in[1];
    const float* scales = (const float*)d_in[2];
    float*       y      = (float*)d_out;

    int nconv = XV + SV;
    cvt_kernel<<<(nconv + 255) / 256, 256>>>(x, scales);

    cudaFuncSetAttribute(int4_gemm_hmma,
                         cudaFuncAttributeMaxDynamicSharedMemorySize,
                         SMEM_TOTAL);
    dim3 grid(M_TOTAL / MT, N_TOTAL / NT);   // (4, 86)
    int4_gemm_hmma<<<grid, THREADS, SMEM_TOTAL>>>(wp, y);
}

// round 12
// speedup vs baseline: 1.5839x; 1.1885x over previous
#include <cuda_runtime.h>
#include <cuda_fp16.h>
#include <cstdint>

// ---------------------------------------------------------------------------
// int4 group-quantized GEMM, fp32 I/O. Two-phase:
//   1) dequant_w: W (packed int4-in-int32) -> fp16 [11008 x 4096]  (90 MB)
//      cvt_x:    x fp32 -> fp16
//   2) pure fp16 HMMA GEMM, both operands via cp.async, fragment
//      double-buffering over ks (LDSM of ks+1 overlaps MMAs of ks).
// y[512, 11008] = x @ W^T, w = scale[n, k/128] * (q - 8)
// ---------------------------------------------------------------------------

#define M_TOTAL 512
#define N_TOTAL 11008
#define K_TOTAL 4096
#define KW_INT  2048
#define NGROUPS 32

#define MT 128
#define NT 128
#define KT 64
#define NSTAGES (K_TOTAL / KT)  // 64
#define THREADS 256

#define SWZ128(bo) ((bo) ^ (((bo) >> 3) & 0x70))

#define STAGE_BYTES (128 * 128)                          // 16 KB
#define SMEM_A_OFF(buf) ((buf) * STAGE_BYTES)            // 3 bufs
#define SMEM_B_OFF(buf) (3 * STAGE_BYTES + (buf) * STAGE_BYTES)  // 3 bufs
#define SMEM_TOTAL (6 * STAGE_BYTES)                     // 96 KB

__device__ __align__(16) __half g_xh[M_TOTAL * K_TOTAL];       // 4 MB
__device__ __align__(16) __half g_wh[(size_t)N_TOTAL * K_TOTAL]; // 90 MB

// ---------------- PTX helpers ----------------
__device__ __forceinline__ uint32_t smem_u32(const void* p) {
    uint32_t a;
    asm("{ .reg .u64 t; cvta.to.shared.u64 t, %1; cvt.u32.u64 %0, t; }"
        : "=r"(a) : "l"(p));
    return a;
}

__device__ __forceinline__ void cp_async16(uint32_t saddr, const void* g) {
    asm volatile("cp.async.cg.shared.global [%0], [%1], 16;"
                 :: "r"(saddr), "l"(g) : "memory");
}
#define CP_COMMIT() asm volatile("cp.async.commit_group;" ::: "memory")
#define CP_WAIT1()  asm volatile("cp.async.wait_group 1;" ::: "memory")

__device__ __forceinline__ void ldsm4(uint32_t* r, uint32_t a) {
    asm volatile("ldmatrix.sync.aligned.m8n8.x4.shared.b16 {%0,%1,%2,%3}, [%4];"
                 : "=r"(r[0]), "=r"(r[1]), "=r"(r[2]), "=r"(r[3]) : "r"(a));
}

__device__ __forceinline__ void mma16816(float* c, const uint32_t* a,
                                         const uint32_t* b) {
    asm volatile(
        "mma.sync.aligned.m16n8k16.row.col.f32.f16.f16.f32 "
        "{%0,%1,%2,%3}, {%4,%5,%6,%7}, {%8,%9}, {%0,%1,%2,%3};"
        : "+f"(c[0]), "+f"(c[1]), "+f"(c[2]), "+f"(c[3])
        : "r"(a[0]), "r"(a[1]), "r"(a[2]), "r"(a[3]), "r"(b[0]), "r"(b[1]));
}

// dequant one packed byte -> half2 {lo-8, hi-8} * s2  (exact via 0x6400 bias)
__device__ __forceinline__ __half2 dq(int b, __half2 s2, __half2 c1032) {
    uint32_t u = (uint32_t)(b & 0xF) | (((uint32_t)b << 12) & 0x000F0000u)
               | 0x64006400u;
    __half2 h = __hsub2(*reinterpret_cast<__half2*>(&u), c1032);
    return __hmul2(h, s2);
}

// ---------------- pre-kernels ----------------
#define XV (M_TOTAL * K_TOTAL / 4)

__global__ void __launch_bounds__(256)
cvt_x(const float* __restrict__ x) {
    int i = blockIdx.x * blockDim.x + threadIdx.x;
    if (i < XV) {
        float4 f = reinterpret_cast<const float4*>(x)[i];
        union { __half2 h[2]; uint2 u; } p;
        p.h[0] = __floats2half2_rn(f.x, f.y);
        p.h[1] = __floats2half2_rn(f.z, f.w);
        reinterpret_cast<uint2*>(g_xh)[i] = p.u;
    }
}

// one thread: 4 packed int32 (= 4 bytes = 8 k-values) -> 8 fp16 (16 B)
#define WCHUNKS (KW_INT / 4)                 // 512 chunks per weight row
#define WTHREADS ((size_t)N_TOTAL * WCHUNKS) // 5,636,096

__global__ void __launch_bounds__(256)
dequant_w(const int* __restrict__ wp, const float* __restrict__ sc) {
    size_t t = (size_t)blockIdx.x * 256 + threadIdx.x;
    if (t >= WTHREADS) return;
    int n = (int)(t >> 9);          // / 512
    int c = (int)(t & 511);         // chunk in row
    const int4 pv = *reinterpret_cast<const int4*>(
        wp + (size_t)n * KW_INT + c * 4);
    // k0 = c*8; group = k0/128 = c/16 (8 k never crosses a 128-group)
    const float s = sc[n * NGROUPS + (c >> 4)];
    const __half2 s2 = __half2half2(__float2half_rn(s));
    const __half2 c1032 = __half2half2(__ushort_as_half((unsigned short)0x6408));
    union { __half2 h[4]; uint4 u; } pk;
    pk.h[0] = dq(pv.x, s2, c1032);
    pk.h[1] = dq(pv.y, s2, c1032);
    pk.h[2] = dq(pv.z, s2, c1032);
    pk.h[3] = dq(pv.w, s2, c1032);
    *reinterpret_cast<uint4*>(g_wh + (size_t)n * K_TOTAL + c * 8) = pk.u;
}

// ---------------- main GEMM kernel (pure fp16) ----------------
__global__ void __launch_bounds__(THREADS, 2)
gemm_hmma(float* __restrict__ y) {
    extern __shared__ __align__(1024) char smem[];
    const uint32_t sbase = smem_u32(smem);

    const int tid = threadIdx.x;
    const int wid = tid >> 5;
    const int lid = tid & 31;
    const int wm = (wid >> 2) * 64;   // 2x4 warp grid, 64x32 warp tile
    const int wn = (wid & 3) * 32;

    const int m0 = blockIdx.x * MT;   // fast dim: M-siblings share weights in L2
    const int n0 = blockIdx.y * NT;

    const int jA = lid >> 3, rA = lid & 7;
    const int a_row_l = (jA & 1) * 8 + rA;
    const int a_kb_l  = (jA >> 1) * 16;
    const int b_row_l = (jA >> 1) * 8 + rA;
    const int b_kb_l  = (jA & 1) * 16;

    float acc[4][4][4];
    #pragma unroll
    for (int i = 0; i < 4; ++i)
        #pragma unroll
        for (int j = 0; j < 4; ++j)
            #pragma unroll
            for (int k = 0; k < 4; ++k) acc[i][j][k] = 0.f;

    auto issue_a = [&](int k0, int buf) {
        const uint32_t abase = sbase + SMEM_A_OFF(buf);
        #pragma unroll
        for (int it = 0; it < 4; ++it) {
            int t = tid + it * THREADS;
            int row = t >> 3, ch = t & 7;
            const void* src = g_xh + (size_t)(m0 + row) * K_TOTAL + k0 + ch * 8;
            uint32_t bo = row * 128 + ch * 16;
            cp_async16(abase + SWZ128(bo), src);
        }
    };
    auto issue_b = [&](int k0, int buf) {
        const uint32_t bbase = sbase + SMEM_B_OFF(buf);
        #pragma unroll
        for (int it = 0; it < 4; ++it) {
            int t = tid + it * THREADS;
            int row = t >> 3, ch = t & 7;
            const void* src = g_wh + (size_t)(n0 + row) * K_TOTAL + k0 + ch * 8;
            uint32_t bo = row * 128 + ch * 16;
            cp_async16(bbase + SWZ128(bo), src);
        }
    };

    // ---- prologue: stages 0,1 in flight ----
    issue_a(0, 0); issue_b(0, 0);
    CP_COMMIT();
    issue_a(KT, 1); issue_b(KT, 1);
    CP_COMMIT();
    CP_WAIT1();                  // stage 0 landed
    __syncthreads();

    // ---- main loop ----
    int buf_c = 0, buf_p = 2;
    #pragma unroll 1
    for (int st = 0; st < NSTAGES; ++st) {
        if (st + 2 < NSTAGES) {
            issue_a((st + 2) * KT, buf_p);
            issue_b((st + 2) * KT, buf_p);
        }
        CP_COMMIT();

        const uint32_t abase = sbase + SMEM_A_OFF(buf_c);
        const uint32_t bbase = sbase + SMEM_B_OFF(buf_c);

        // ks-pipelined fragments: LDSM(ks+1) overlaps MMA(ks)
        uint32_t af[2][4][4];
        uint32_t bf[2][2][4];
        #pragma unroll
        for (int mt = 0; mt < 4; ++mt)
            ldsm4(af[0][mt], abase + SWZ128(
                (uint32_t)(wm + mt * 16 + a_row_l) * 128 + a_kb_l));
        #pragma unroll
        for (int np = 0; np < 2; ++np)
            ldsm4(bf[0][np], bbase + SWZ128(
                (uint32_t)(wn + np * 16 + b_row_l) * 128 + b_kb_l));

        #pragma unroll
        for (int ks = 0; ks < 4; ++ks) {
            const int cur = ks & 1, nxt = cur ^ 1;
            if (ks < 3) {
                const int kb = (ks + 1) * 32;
                #pragma unroll
                for (int mt = 0; mt < 4; ++mt)
                    ldsm4(af[nxt][mt], abase + SWZ128(
                        (uint32_t)(wm + mt * 16 + a_row_l) * 128 + kb + a_kb_l));
                #pragma unroll
                for (int np = 0; np < 2; ++np)
                    ldsm4(bf[nxt][np], bbase + SWZ128(
                        (uint32_t)(wn + np * 16 + b_row_l) * 128 + kb + b_kb_l));
            }
            #pragma unroll
            for (int mt = 0; mt < 4; ++mt)
                #pragma unroll
                for (int nt = 0; nt < 4; ++nt)
                    mma16816(acc[mt][nt], af[cur][mt],
                             &bf[cur][nt >> 1][(nt & 1) * 2]);
        }

        CP_WAIT1();              // stage st+1 landed; st+2 may fly
        __syncthreads();

        buf_c = (buf_c == 2) ? 0 : buf_c + 1;
        buf_p = (buf_p == 2) ? 0 : buf_p + 1;
    }

    // ---- epilogue: fp32 accum -> fp16-rounded -> fp32 stores ----
    const int crow = lid >> 2;
    const int ccol = (lid & 3) * 2;
    #pragma unroll
    for (int mt = 0; mt < 4; ++mt) {
        #pragma unroll
        for (int nt = 0; nt < 4; ++nt) {
            const int r = m0 + wm + mt * 16 + crow;
            const int c = n0 + wn + nt * 8 + ccol;
            float v0 = __half2float(__float2half_rn(acc[mt][nt][0]));
            float v1 = __half2float(__float2half_rn(acc[mt][nt][1]));
            float v2 = __half2float(__float2half_rn(acc[mt][nt][2]));
            float v3 = __half2float(__float2half_rn(acc[mt][nt][3]));
            *reinterpret_cast<float2*>(y + (size_t)r * N_TOTAL + c) =
                make_float2(v0, v1);
            *reinterpret_cast<float2*>(y + (size_t)(r + 8) * N_TOTAL + c) =
                make_float2(v2, v3);
        }
    }
}

extern "C" void kernel_launch(void* const* d_in, const int* in_sizes, int n_in,
                              void* d_out, int out_size) {
    const float* x      = (const float*)d_in[0];
    const int*   wp     = (const int*)d_in[1];
    const float* scales = (const float*)d_in[2];
    float*       y      = (float*)d_out;

    cvt_x<<<(XV + 255) / 256, 256>>>(x);
    dequant_w<<<(unsigned)((WTHREADS + 255) / 256), 256>>>(wp, scales);

    cudaFuncSetAttribute(gemm_hmma,
                         cudaFuncAttributeMaxDynamicSharedMemorySize,
                         SMEM_TOTAL);
    dim3 grid(M_TOTAL / MT, N_TOTAL / NT);   // (4, 86)
    gemm_hmma<<<grid, THREADS, SMEM_TOTAL>>>(y);
}

// round 14
// speedup vs baseline: 1.6963x; 1.0709x over previous
#include <cuda_runtime.h>
#include <cuda_fp16.h>
#include <cstdint>

// ---------------------------------------------------------------------------
// int4 group-quantized GEMM, fp32 I/O. Three-phase:
//   1) cvt_x: x fp32->fp16; dequant_w: packed int4 -> fp16 W (90 MB)
//   2) split-K=2 fp16 HMMA GEMM -> fp32 partials (deterministic, no atomics)
//   3) reduce: partial0+partial1 -> fp16-rounded fp32 y
// y[512, 11008] = x @ W^T, w = scale[n, k/128] * (q - 8)
// R13: split-K=2 kills the 2-wave tail (344 CTAs on 296 slots -> 688 on 296).
// ---------------------------------------------------------------------------

#define M_TOTAL 512
#define N_TOTAL 11008
#define K_TOTAL 4096
#define KW_INT  2048
#define NGROUPS 32

#define MT 128
#define NT 128
#define KT 64
#define NSPLIT 2
#define KSPLIT (K_TOTAL / NSPLIT)        // 2048
#define NSTAGES (KSPLIT / KT)            // 32 per CTA
#define THREADS 256

#define SWZ128(bo) ((bo) ^ (((bo) >> 3) & 0x70))

#define STAGE_BYTES (128 * 128)                          // 16 KB
#define SMEM_A_OFF(buf) ((buf) * STAGE_BYTES)            // 3 bufs
#define SMEM_B_OFF(buf) (3 * STAGE_BYTES + (buf) * STAGE_BYTES)  // 3 bufs
#define SMEM_TOTAL (6 * STAGE_BYTES)                     // 96 KB

__device__ __align__(16) __half g_xh[M_TOTAL * K_TOTAL];          // 4 MB
__device__ __align__(16) __half g_wh[(size_t)N_TOTAL * K_TOTAL];  // 90 MB
__device__ __align__(16) float  g_part[(size_t)NSPLIT * M_TOTAL * N_TOTAL]; // 45 MB

// ---------------- PTX helpers ----------------
__device__ __forceinline__ uint32_t smem_u32(const void* p) {
    uint32_t a;
    asm("{ .reg .u64 t; cvta.to.shared.u64 t, %1; cvt.u32.u64 %0, t; }"
        : "=r"(a) : "l"(p));
    return a;
}

__device__ __forceinline__ void cp_async16(uint32_t saddr, const void* g) {
    asm volatile("cp.async.cg.shared.global [%0], [%1], 16;"
                 :: "r"(saddr), "l"(g) : "memory");
}
#define CP_COMMIT() asm volatile("cp.async.commit_group;" ::: "memory")
#define CP_WAIT1()  asm volatile("cp.async.wait_group 1;" ::: "memory")

__device__ __forceinline__ void ldsm4(uint32_t* r, uint32_t a) {
    asm volatile("ldmatrix.sync.aligned.m8n8.x4.shared.b16 {%0,%1,%2,%3}, [%4];"
                 : "=r"(r[0]), "=r"(r[1]), "=r"(r[2]), "=r"(r[3]) : "r"(a));
}

__device__ __forceinline__ void mma16816(float* c, const uint32_t* a,
                                         const uint32_t* b) {
    asm volatile(
        "mma.sync.aligned.m16n8k16.row.col.f32.f16.f16.f32 "
        "{%0,%1,%2,%3}, {%4,%5,%6,%7}, {%8,%9}, {%0,%1,%2,%3};"
        : "+f"(c[0]), "+f"(c[1]), "+f"(c[2]), "+f"(c[3])
        : "r"(a[0]), "r"(a[1]), "r"(a[2]), "r"(a[3]), "r"(b[0]), "r"(b[1]));
}

// dequant one packed byte -> half2 {lo-8, hi-8} * s2  (exact via 0x6400 bias)
__device__ __forceinline__ __half2 dq(int b, __half2 s2, __half2 c1032) {
    uint32_t u = (uint32_t)(b & 0xF) | (((uint32_t)b << 12) & 0x000F0000u)
               | 0x64006400u;
    __half2 h = __hsub2(*reinterpret_cast<__half2*>(&u), c1032);
    return __hmul2(h, s2);
}

// ---------------- pre-kernels ----------------
#define XV (M_TOTAL * K_TOTAL / 4)

__global__ void __launch_bounds__(256)
cvt_x(const float* __restrict__ x) {
    int i = blockIdx.x * blockDim.x + threadIdx.x;
    if (i < XV) {
        float4 f = reinterpret_cast<const float4*>(x)[i];
        union { __half2 h[2]; uint2 u; } p;
        p.h[0] = __floats2half2_rn(f.x, f.y);
        p.h[1] = __floats2half2_rn(f.z, f.w);
        reinterpret_cast<uint2*>(g_xh)[i] = p.u;
    }
}

#define WCHUNKS (KW_INT / 4)                 // 512 chunks per weight row
#define WTHREADS ((size_t)N_TOTAL * WCHUNKS) // 5,636,096

__global__ void __launch_bounds__(256)
dequant_w(const int* __restrict__ wp, const float* __restrict__ sc) {
    size_t t = (size_t)blockIdx.x * 256 + threadIdx.x;
    if (t >= WTHREADS) return;
    int n = (int)(t >> 9);
    int c = (int)(t & 511);
    const int4 pv = *reinterpret_cast<const int4*>(
        wp + (size_t)n * KW_INT + c * 4);
    const float s = sc[n * NGROUPS + (c >> 4)];
    const __half2 s2 = __half2half2(__float2half_rn(s));
    const __half2 c1032 = __half2half2(__ushort_as_half((unsigned short)0x6408));
    union { __half2 h[4]; uint4 u; } pk;
    pk.h[0] = dq(pv.x, s2, c1032);
    pk.h[1] = dq(pv.y, s2, c1032);
    pk.h[2] = dq(pv.z, s2, c1032);
    pk.h[3] = dq(pv.w, s2, c1032);
    *reinterpret_cast<uint4*>(g_wh + (size_t)n * K_TOTAL + c * 8) = pk.u;
}

// ---------------- main GEMM kernel (split-K, pure fp16) ----------------
__global__ void __launch_bounds__(THREADS, 2)
gemm_hmma(void) {
    extern __shared__ __align__(1024) char smem[];
    const uint32_t sbase = smem_u32(smem);

    const int tid = threadIdx.x;
    const int wid = tid >> 5;
    const int lid = tid & 31;
    const int wm = (wid >> 2) * 64;   // 2x4 warp grid, 64x32 warp tile
    const int wn = (wid & 3) * 32;

    const int m0 = blockIdx.x * MT;   // fast dim: M-siblings share weights in L2
    const int n0 = blockIdx.y * NT;
    const int kz = blockIdx.z * KSPLIT;

    const int jA = lid >> 3, rA = lid & 7;
    const int a_row_l = (jA & 1) * 8 + rA;
    const int a_kb_l  = (jA >> 1) * 16;
    const int b_row_l = (jA >> 1) * 8 + rA;
    const int b_kb_l  = (jA & 1) * 16;

    float acc[4][4][4];
    #pragma unroll
    for (int i = 0; i < 4; ++i)
        #pragma unroll
        for (int j = 0; j < 4; ++j)
            #pragma unroll
            for (int k = 0; k < 4; ++k) acc[i][j][k] = 0.f;

    auto issue_a = [&](int k0, int buf) {
        const uint32_t abase = sbase + SMEM_A_OFF(buf);
        #pragma unroll
        for (int it = 0; it < 4; ++it) {
            int t = tid + it * THREADS;
            int row = t >> 3, ch = t & 7;
            const void* src = g_xh + (size_t)(m0 + row) * K_TOTAL + k0 + ch * 8;
            uint32_t bo = row * 128 + ch * 16;
            cp_async16(abase + SWZ128(bo), src);
        }
    };
    auto issue_b = [&](int k0, int buf) {
        const uint32_t bbase = sbase + SMEM_B_OFF(buf);
        #pragma unroll
        for (int it = 0; it < 4; ++it) {
            int t = tid + it * THREADS;
            int row = t >> 3, ch = t & 7;
            const void* src = g_wh + (size_t)(n0 + row) * K_TOTAL + k0 + ch * 8;
            uint32_t bo = row * 128 + ch * 16;
            cp_async16(bbase + SWZ128(bo), src);
        }
    };

    // ---- prologue: stages 0,1 of this K-half in flight ----
    issue_a(kz, 0); issue_b(kz, 0);
    CP_COMMIT();
    issue_a(kz + KT, 1); issue_b(kz + KT, 1);
    CP_COMMIT();
    CP_WAIT1();
    __syncthreads();

    // ---- main loop ----
    int buf_c = 0, buf_p = 2;
    #pragma unroll 1
    for (int st = 0; st < NSTAGES; ++st) {
        if (st + 2 < NSTAGES) {
            issue_a(kz + (st + 2) * KT, buf_p);
            issue_b(kz + (st + 2) * KT, buf_p);
        }
        CP_COMMIT();

        const uint32_t abase = sbase + SMEM_A_OFF(buf_c);
        const uint32_t bbase = sbase + SMEM_B_OFF(buf_c);

        uint32_t af[2][4][4];
        uint32_t bf[2][2][4];
        #pragma unroll
        for (int mt = 0; mt < 4; ++mt)
            ldsm4(af[0][mt], abase + SWZ128(
                (uint32_t)(wm + mt * 16 + a_row_l) * 128 + a_kb_l));
        #pragma unroll
        for (int np = 0; np < 2; ++np)
            ldsm4(bf[0][np], bbase + SWZ128(
                (uint32_t)(wn + np * 16 + b_row_l) * 128 + b_kb_l));

        #pragma unroll
        for (int ks = 0; ks < 4; ++ks) {
            const int cur = ks & 1, nxt = cur ^ 1;
            if (ks < 3) {
                const int kb = (ks + 1) * 32;
                #pragma unroll
                for (int mt = 0; mt < 4; ++mt)
                    ldsm4(af[nxt][mt], abase + SWZ128(
                        (uint32_t)(wm + mt * 16 + a_row_l) * 128 + kb + a_kb_l));
                #pragma unroll
                for (int np = 0; np < 2; ++np)
                    ldsm4(bf[nxt][np], bbase + SWZ128(
                        (uint32_t)(wn + np * 16 + b_row_l) * 128 + kb + b_kb_l));
            }
            #pragma unroll
            for (int mt = 0; mt < 4; ++mt)
                #pragma unroll
                for (int nt = 0; nt < 4; ++nt)
                    mma16816(acc[mt][nt], af[cur][mt],
                             &bf[cur][nt >> 1][(nt & 1) * 2]);
        }

        CP_WAIT1();
        __syncthreads();

        buf_c = (buf_c == 2) ? 0 : buf_c + 1;
        buf_p = (buf_p == 2) ? 0 : buf_p + 1;
    }

    // ---- epilogue: raw fp32 partials (deterministic; no atomics) ----
    float* part = g_part + (size_t)blockIdx.z * M_TOTAL * N_TOTAL;
    const int crow = lid >> 2;
    const int ccol = (lid & 3) * 2;
    #pragma unroll
    for (int mt = 0; mt < 4; ++mt) {
        #pragma unroll
        for (int nt = 0; nt < 4; ++nt) {
            const int r = m0 + wm + mt * 16 + crow;
            const int c = n0 + wn + nt * 8 + ccol;
            *reinterpret_cast<float2*>(part + (size_t)r * N_TOTAL + c) =
                make_float2(acc[mt][nt][0], acc[mt][nt][1]);
            *reinterpret_cast<float2*>(part + (size_t)(r + 8) * N_TOTAL + c) =
                make_float2(acc[mt][nt][2], acc[mt][nt][3]);
        }
    }
}

// ---------------- reduce: sum partials, round through fp16 ----------------
#define YV ((size_t)M_TOTAL * N_TOTAL / 4)   // 1,409,024 float4s

__global__ void __launch_bounds__(256)
reduce_y(float* __restrict__ y) {
    size_t i = (size_t)blockIdx.x * 256 + threadIdx.x;
    if (i >= YV) return;
    const float4 p0 = reinterpret_cast<const float4*>(g_part)[i];
    const float4 p1 = reinterpret_cast<const float4*>(
        g_part + (size_t)M_TOTAL * N_TOTAL)[i];
    float4 o;
    o.x = __half2float(__float2half_rn(p0.x + p1.x));
    o.y = __half2float(__float2half_rn(p0.y + p1.y));
    o.z = __half2float(__float2half_rn(p0.z + p1.z));
    o.w = __half2float(__float2half_rn(p0.w + p1.w));
    reinterpret_cast<float4*>(y)[i] = o;
}

extern "C" void kernel_launch(void* const* d_in, const int* in_sizes, int n_in,
                              void* d_out, int out_size) {
    const float* x      = (const float*)d_in[0];
    const int*   wp     = (const int*)d_in[1];
    const float* scales = (const float*)d_in[2];
    float*       y      = (float*)d_out;

    cvt_x<<<(XV + 255) / 256, 256>>>(x);
    dequant_w<<<(unsigned)((WTHREADS + 255) / 256), 256>>>(wp, scales);

    cudaFuncSetAttribute(gemm_hmma,
                         cudaFuncAttributeMaxDynamicSharedMemorySize,
                         SMEM_TOTAL);
    dim3 grid(M_TOTAL / MT, N_TOTAL / NT, NSPLIT);   // (4, 86, 2)
    gemm_hmma<<<grid, THREADS, SMEM_TOTAL>>>();

    reduce_y<<<(unsigned)((YV + 255) / 256), 256>>>(y);
}